// round 12
// baseline (speedup 1.0000x reference)
#include <cuda_runtime.h>
#include <cuda_bf16.h>
#include <cstdint>

// Problem constants (fixed by the reference)
#define N_TOK 16384      // B*S = 8*2048
#define D_DIM 4096
#define D_VEC 1024       // D/4 16-byte packs per row
#define N_EXP 8
#define CAP   2048       // capacity = B*S/E
#define MARGIN_TH 1e-3f  // fp64 re-rank threshold (noise ~1e-6 both sides)

// Scratch (no device allocs allowed) ---------------------------------------
__device__ int   g_routes[N_TOK];
__device__ int   g_inv[N_TOK];    // inv[e*CAP+p] = source token (valid iff p < g_cnt[e])
__device__ int   g_cnt[N_EXP];    // per-expert routed totals
__device__ float g_margin[N_TOK]; // top-2 logit margin per token

// ---------------------------------------------------------------------------
// Pass 1: routing, scalar fp32. Key change vs R11: accumulators are 32 f32
// regs (not 64 u64 halves) -> ~70 regs total -> 3 CTAs/SM = 24 warps/SM for
// latency hiding (previous variants ran at 8-16 warps/SM and were latency
// bound at ~115us). W (128KB) rides L1; x streams once from DRAM.
// Each warp computes 4 tokens (W read amortized 4x). 32 tokens/CTA, 512 CTAs.
// ---------------------------------------------------------------------------
__global__ void __launch_bounds__(256, 3) route_kernel(
    const float4* __restrict__ x,   // [N_TOK][1024]
    const float4* __restrict__ W,   // [8][1024]
    const float*  __restrict__ b,   // [8]
    int*   __restrict__ routes,
    float* __restrict__ margin)
{
    const int warp = threadIdx.x >> 5;
    const int lane = threadIdx.x & 31;
    const int tbase = (blockIdx.x * 8 + warp) * 4;   // first of 4 tokens

    const float4* x0 = x + (size_t)tbase * D_VEC;

    float acc[4][N_EXP];
#pragma unroll
    for (int t = 0; t < 4; t++)
#pragma unroll
        for (int e = 0; e < N_EXP; e++) acc[t][e] = 0.f;

    for (int i = 0; i < 32; i++) {
        const int idx = i * 32 + lane;
        float4 xv0 = __ldg(x0 + idx);
        float4 xv1 = __ldg(x0 + D_VEC + idx);
        float4 xv2 = __ldg(x0 + 2 * D_VEC + idx);
        float4 xv3 = __ldg(x0 + 3 * D_VEC + idx);
#pragma unroll
        for (int e = 0; e < N_EXP; e++) {
            float4 wv = __ldg(W + e * D_VEC + idx);   // L1-resident
            acc[0][e] += xv0.x * wv.x + xv0.y * wv.y + xv0.z * wv.z + xv0.w * wv.w;
            acc[1][e] += xv1.x * wv.x + xv1.y * wv.y + xv1.z * wv.z + xv1.w * wv.w;
            acc[2][e] += xv2.x * wv.x + xv2.y * wv.y + xv2.z * wv.z + xv2.w * wv.w;
            acc[3][e] += xv3.x * wv.x + xv3.y * wv.y + xv3.z * wv.z + xv3.w * wv.w;
        }
    }

    // butterfly reduce across the warp
#pragma unroll
    for (int t = 0; t < 4; t++) {
#pragma unroll
        for (int e = 0; e < N_EXP; e++) {
            float v = acc[t][e];
#pragma unroll
            for (int off = 16; off > 0; off >>= 1)
                v += __shfl_xor_sync(0xFFFFFFFFu, v, off);
            acc[t][e] = v;
        }
    }

    if (lane == 0) {
#pragma unroll
        for (int t = 0; t < 4; t++) {
            float best = -1e30f, second = -1e30f;
            int bi = 0;
#pragma unroll
            for (int e = 0; e < N_EXP; e++) {
                float l = acc[t][e] + b[e];
                if (l > best) { second = best; best = l; bi = e; }
                else if (l > second) { second = l; }
            }
            routes[tbase + t] = bi;
            margin[tbase + t] = best - second;
        }
    }
}

// ---------------------------------------------------------------------------
// Pass 2 (fused refine + scan), one 1024-thread block.
//   a) collect tokens with margin < threshold (expected ~20 chip-wide)
//   b) re-rank each exactly in fp64 (removes all my-side argmax noise),
//      write corrected routes (same-block coherence via __syncthreads)
//   c) stable-position scan: per-thread packed histogram (8x8-bit u64),
//      3-level shfl scan, fill inverse map + per-expert totals.
// ---------------------------------------------------------------------------
__global__ void __launch_bounds__(1024) fixup_scan_kernel(
    const float* __restrict__ x,
    const float* __restrict__ Wf,
    const float* __restrict__ b,
    int* __restrict__ routes,
    int* __restrict__ inv)
{
    __shared__ int    list[256];
    __shared__ int    nlist;
    __shared__ double sred[32][N_EXP];
    __shared__ unsigned long long wtot_lo[32], wtot_hi[32];
    __shared__ unsigned long long base_lo[32], base_hi[32];

    const int t    = threadIdx.x;
    const int warp = t >> 5;
    const int lane = t & 31;

    // ---- a) marginal-token list ----
    if (t == 0) nlist = 0;
    __syncthreads();
#pragma unroll
    for (int q = 0; q < 16; q++) {
        const int tok = q * 1024 + t;
        if (g_margin[tok] < MARGIN_TH) {
            int s = atomicAdd(&nlist, 1);
            if (s < 256) list[s] = tok;
        }
    }
    __syncthreads();

    // ---- b) exact fp64 re-rank ----
    const int n = (nlist < 256) ? nlist : 256;
    for (int w = 0; w < n; w++) {
        const int tok = list[w];
        const float* xr = x + (size_t)tok * D_DIM;

        double p[N_EXP];
#pragma unroll
        for (int e = 0; e < N_EXP; e++) p[e] = 0.0;

#pragma unroll
        for (int q = 0; q < 4; q++) {
            const int d = q * 1024 + t;
            const double xv = (double)__ldg(xr + d);
#pragma unroll
            for (int e = 0; e < N_EXP; e++)
                p[e] += xv * (double)__ldg(Wf + e * D_DIM + d);
        }
#pragma unroll
        for (int e = 0; e < N_EXP; e++) {
            double v = p[e];
#pragma unroll
            for (int off = 16; off > 0; off >>= 1)
                v += __shfl_xor_sync(0xFFFFFFFFu, v, off);
            if (lane == 0) sred[warp][e] = v;
        }
        __syncthreads();
        if (t == 0) {
            double best = -1e300; int bi = 0;
#pragma unroll
            for (int e = 0; e < N_EXP; e++) {
                double s = (double)b[e];
#pragma unroll
                for (int wi = 0; wi < 32; wi++) s += sred[wi][e];
                if (s > best) { best = s; bi = e; }   // strict > : first-max
            }
            routes[tok] = bi;                          // plain store
        }
        __syncthreads();
    }

    // ---- c) stable-position scan (reads updated routes; plain loads) ----
    int toks[16];
    const int4* rp = (const int4*)routes + t * 4;
#pragma unroll
    for (int q = 0; q < 4; q++) {
        int4 v = rp[q];                                // coherent plain load
        toks[q * 4 + 0] = v.x; toks[q * 4 + 1] = v.y;
        toks[q * 4 + 2] = v.z; toks[q * 4 + 3] = v.w;
    }

    unsigned long long h = 0ull;                       // 8x8-bit histogram
#pragma unroll
    for (int k = 0; k < 16; k++) h += 1ull << (toks[k] * 8);

    unsigned long long g = h >> 32;                    // spread to 4x16-bit
    unsigned long long lo =  (h & 0xFFull)            | ((h & 0xFF00ull) << 8)
                          | ((h & 0xFF0000ull) << 16) | ((h & 0xFF000000ull) << 24);
    unsigned long long hi =  (g & 0xFFull)            | ((g & 0xFF00ull) << 8)
                          | ((g & 0xFF0000ull) << 16) | ((g & 0xFF000000ull) << 24);

    unsigned long long slo = lo, shi = hi;
#pragma unroll
    for (int o = 1; o < 32; o <<= 1) {
        unsigned long long nl = __shfl_up_sync(0xFFFFFFFFu, slo, o);
        unsigned long long nh = __shfl_up_sync(0xFFFFFFFFu, shi, o);
        if (lane >= o) { slo += nl; shi += nh; }
    }
    const unsigned long long elo = slo - lo;
    const unsigned long long ehi = shi - hi;
    if (lane == 31) { wtot_lo[warp] = slo; wtot_hi[warp] = shi; }
    __syncthreads();

    if (warp == 0) {
        unsigned long long tlo = wtot_lo[lane], thi = wtot_hi[lane];
        unsigned long long plo = tlo, phi = thi;
#pragma unroll
        for (int o = 1; o < 32; o <<= 1) {
            unsigned long long nl = __shfl_up_sync(0xFFFFFFFFu, plo, o);
            unsigned long long nh = __shfl_up_sync(0xFFFFFFFFu, phi, o);
            if (lane >= o) { plo += nl; phi += nh; }
        }
        base_lo[lane] = plo - tlo;
        base_hi[lane] = phi - thi;
        if (lane == 31) {
#pragma unroll
            for (int e = 0; e < 4; e++) {
                g_cnt[e]     = (int)((plo >> (e * 16)) & 0xFFFF);
                g_cnt[e + 4] = (int)((phi >> (e * 16)) & 0xFFFF);
            }
        }
    }
    __syncthreads();

    unsigned long long mylo = elo + base_lo[warp];
    unsigned long long myhi = ehi + base_hi[warp];
    const int base = t * 16;
#pragma unroll
    for (int k = 0; k < 16; k++) {
        const int r = toks[k];
        const int sh = (r & 3) * 16;
        const bool low = r < 4;
        const int p = (int)(((low ? mylo : myhi) >> sh) & 0xFFFF);
        const unsigned long long inc = 1ull << sh;
        if (low) mylo += inc; else myhi += inc;
        if (p < CAP) inv[r * CAP + p] = base + k;
    }
}

// ---------------------------------------------------------------------------
// Pass 3: gather (exact R10 form: plain __ldg + plain stores = 77.4us @78%
// DRAM; .cs variants measured slower). One CTA per output row.
// ---------------------------------------------------------------------------
__global__ void __launch_bounds__(256) gather_kernel(
    const float4* __restrict__ x,
    const int*   __restrict__ inv,
    float4* __restrict__ out)
{
    const int row = blockIdx.x;
    const int e = row >> 11;          // row / CAP
    const int p = row & (CAP - 1);
    float4* o = out + (size_t)row * D_VEC;
    const int t = threadIdx.x;

    if (p < g_cnt[e]) {
        const int src = __ldg(inv + row);      // uniform broadcast
        const float4* s = x + (size_t)src * D_VEC;
#pragma unroll
        for (int i = 0; i < 4; i++)
            o[t + 256 * i] = __ldg(s + t + 256 * i);
    } else {
        const float4 z = make_float4(0.f, 0.f, 0.f, 0.f);
#pragma unroll
        for (int i = 0; i < 4; i++)
            o[t + 256 * i] = z;
    }
}

// ---------------------------------------------------------------------------
extern "C" void kernel_launch(void* const* d_in, const int* in_sizes, int n_in,
                              void* d_out, int out_size)
{
    const float* x = (const float*)d_in[0];   // [8,2048,4096]
    const float* W = (const float*)d_in[1];   // [8,4096]
    const float* b = (const float*)d_in[2];   // [8]
    float* out = (float*)d_out;               // [16384,4096]

    int* routes;   cudaGetSymbolAddress((void**)&routes, g_routes);
    int* inv;      cudaGetSymbolAddress((void**)&inv,    g_inv);
    float* margin; cudaGetSymbolAddress((void**)&margin, g_margin);

    route_kernel<<<N_TOK / 32, 256>>>(
        (const float4*)x, (const float4*)W, b, routes, margin);
    fixup_scan_kernel<<<1, 1024>>>(x, W, b, routes, inv);
    gather_kernel<<<N_TOK, 256>>>(
        (const float4*)x, inv, (float4*)out);
}

// round 13
// speedup vs baseline: 4.8670x; 4.8670x over previous
#include <cuda_runtime.h>
#include <cuda_bf16.h>
#include <cstdint>

// Problem constants (fixed by the reference)
#define N_TOK 16384      // B*S = 8*2048
#define D_DIM 4096
#define D_VEC 1024       // D/4 16-byte packs per row
#define N_EXP 8
#define CAP   2048       // capacity = B*S/E
#define MARGIN_TH 1e-4f  // fp64 re-rank threshold (noise ~1e-6 both sides)

// Scratch (no device allocs allowed) ---------------------------------------
__device__ int   g_routes[N_TOK];
__device__ int   g_inv[N_TOK];    // inv[e*CAP+p] = source token (valid iff p < g_cnt[e])
__device__ int   g_cnt[N_EXP];    // per-expert routed totals
__device__ float g_margin[N_TOK]; // top-2 logit margin per token

// ---------------------------------------------------------------------------
// Pass 1: routing, scalar fp32. 2 tokens/warp (16 acc regs) + unroll 2 ->
// ~50 regs -> 5 CTAs/SM = 40 warps/SM (R12 measured issue=32% @24 warps:
// pure latency bound; more warps is the proven lever). W (128KB) rides L1.
// 16 tokens/CTA -> 1024 CTAs.
// ---------------------------------------------------------------------------
__global__ void __launch_bounds__(256, 5) route_kernel(
    const float4* __restrict__ x,   // [N_TOK][1024]
    const float4* __restrict__ W,   // [8][1024]
    const float*  __restrict__ b,   // [8]
    int*   __restrict__ routes,
    float* __restrict__ margin)
{
    const int warp = threadIdx.x >> 5;
    const int lane = threadIdx.x & 31;
    const int tbase = (blockIdx.x * 8 + warp) * 2;   // first of 2 tokens

    const float4* x0 = x + (size_t)tbase * D_VEC;

    float acc[2][N_EXP];
#pragma unroll
    for (int t = 0; t < 2; t++)
#pragma unroll
        for (int e = 0; e < N_EXP; e++) acc[t][e] = 0.f;

#pragma unroll 2
    for (int i = 0; i < 32; i++) {
        const int idx = i * 32 + lane;
        float4 xv0 = __ldg(x0 + idx);
        float4 xv1 = __ldg(x0 + D_VEC + idx);
#pragma unroll
        for (int e = 0; e < N_EXP; e++) {
            float4 wv = __ldg(W + e * D_VEC + idx);   // L1-resident
            acc[0][e] += xv0.x * wv.x + xv0.y * wv.y + xv0.z * wv.z + xv0.w * wv.w;
            acc[1][e] += xv1.x * wv.x + xv1.y * wv.y + xv1.z * wv.z + xv1.w * wv.w;
        }
    }

    // butterfly reduce across the warp
#pragma unroll
    for (int t = 0; t < 2; t++) {
#pragma unroll
        for (int e = 0; e < N_EXP; e++) {
            float v = acc[t][e];
#pragma unroll
            for (int off = 16; off > 0; off >>= 1)
                v += __shfl_xor_sync(0xFFFFFFFFu, v, off);
            acc[t][e] = v;
        }
    }

    if (lane == 0) {
#pragma unroll
        for (int t = 0; t < 2; t++) {
            float best = -1e30f, second = -1e30f;
            int bi = 0;
#pragma unroll
            for (int e = 0; e < N_EXP; e++) {
                float l = acc[t][e] + b[e];
                if (l > best) { second = best; best = l; bi = e; }
                else if (l > second) { second = l; }
            }
            routes[tbase + t] = bi;
            margin[tbase + t] = best - second;
        }
    }
}

// ---------------------------------------------------------------------------
// Pass 1b: fp64 refinement, DISTRIBUTED over 64 blocks (R12's single-block
// fusion serialized ~40 token re-ranks -> ~900us; reverted). Each block
// handles 256 tokens' margins; expected ~4 marginal tokens chip-wide at
// threshold 1e-4 (noise ~1e-6 -> 100x safety).
// ---------------------------------------------------------------------------
__global__ void __launch_bounds__(256) refine_kernel(
    const float* __restrict__ x,
    const float* __restrict__ W,
    const float* __restrict__ b,
    int* __restrict__ routes)
{
    __shared__ int    list[256];
    __shared__ int    nlist;
    __shared__ double sred[8][N_EXP];

    const int tid  = threadIdx.x;
    const int warp = tid >> 5;
    const int lane = tid & 31;
    const int tok0 = blockIdx.x * 256;

    if (tid == 0) nlist = 0;
    __syncthreads();

    if (g_margin[tok0 + tid] < MARGIN_TH) {
        int s = atomicAdd(&nlist, 1);
        list[s] = tok0 + tid;
    }
    __syncthreads();

    const int n = nlist;
    for (int w = 0; w < n; w++) {
        const int tok = list[w];
        const float* xr = x + (size_t)tok * D_DIM;

        double p[N_EXP];
#pragma unroll
        for (int e = 0; e < N_EXP; e++) p[e] = 0.0;

        for (int d = tid; d < D_DIM; d += 256) {
            const double xv = (double)__ldg(xr + d);
#pragma unroll
            for (int e = 0; e < N_EXP; e++)
                p[e] += xv * (double)__ldg(W + e * D_DIM + d);
        }

#pragma unroll
        for (int e = 0; e < N_EXP; e++) {
            double v = p[e];
#pragma unroll
            for (int off = 16; off > 0; off >>= 1)
                v += __shfl_xor_sync(0xFFFFFFFFu, v, off);
            if (lane == 0) sred[warp][e] = v;
        }
        __syncthreads();

        if (tid == 0) {
            double best = -1e300; int bi = 0;
#pragma unroll
            for (int e = 0; e < N_EXP; e++) {
                double s = (double)b[e];
#pragma unroll
                for (int wi = 0; wi < 8; wi++) s += sred[wi][e];
                if (s > best) { best = s; bi = e; }   // strict > : first-max
            }
            routes[tok] = bi;
        }
        __syncthreads();
    }
}

// ---------------------------------------------------------------------------
// Pass 2: stable positions, register/shfl-based. 1024 threads x 16 tokens.
// Packed histogram (8x8-bit u64), offsets in two u64s (4x16-bit), 3-level
// shfl scan. No inv init: gather validity is p < g_cnt[e].
// ---------------------------------------------------------------------------
__global__ void __launch_bounds__(1024) scan_kernel(
    const int4* __restrict__ routes4, int* __restrict__ inv)
{
    __shared__ unsigned long long wtot_lo[32], wtot_hi[32];
    __shared__ unsigned long long base_lo[32], base_hi[32];

    const int t    = threadIdx.x;
    const int warp = t >> 5;
    const int lane = t & 31;

    int toks[16];
    const int4* rp = routes4 + t * 4;
#pragma unroll
    for (int q = 0; q < 4; q++) {
        int4 v = __ldg(rp + q);
        toks[q * 4 + 0] = v.x; toks[q * 4 + 1] = v.y;
        toks[q * 4 + 2] = v.z; toks[q * 4 + 3] = v.w;
    }

    unsigned long long h = 0ull;                       // 8x8-bit histogram
#pragma unroll
    for (int k = 0; k < 16; k++) h += 1ull << (toks[k] * 8);

    unsigned long long g = h >> 32;                    // spread to 4x16-bit
    unsigned long long lo =  (h & 0xFFull)            | ((h & 0xFF00ull) << 8)
                          | ((h & 0xFF0000ull) << 16) | ((h & 0xFF000000ull) << 24);
    unsigned long long hi =  (g & 0xFFull)            | ((g & 0xFF00ull) << 8)
                          | ((g & 0xFF0000ull) << 16) | ((g & 0xFF000000ull) << 24);

    unsigned long long slo = lo, shi = hi;
#pragma unroll
    for (int o = 1; o < 32; o <<= 1) {
        unsigned long long nl = __shfl_up_sync(0xFFFFFFFFu, slo, o);
        unsigned long long nh = __shfl_up_sync(0xFFFFFFFFu, shi, o);
        if (lane >= o) { slo += nl; shi += nh; }
    }
    const unsigned long long elo = slo - lo;
    const unsigned long long ehi = shi - hi;
    if (lane == 31) { wtot_lo[warp] = slo; wtot_hi[warp] = shi; }
    __syncthreads();

    if (warp == 0) {
        unsigned long long tlo = wtot_lo[lane], thi = wtot_hi[lane];
        unsigned long long plo = tlo, phi = thi;
#pragma unroll
        for (int o = 1; o < 32; o <<= 1) {
            unsigned long long nl = __shfl_up_sync(0xFFFFFFFFu, plo, o);
            unsigned long long nh = __shfl_up_sync(0xFFFFFFFFu, phi, o);
            if (lane >= o) { plo += nl; phi += nh; }
        }
        base_lo[lane] = plo - tlo;
        base_hi[lane] = phi - thi;
        if (lane == 31) {
#pragma unroll
            for (int e = 0; e < 4; e++) {
                g_cnt[e]     = (int)((plo >> (e * 16)) & 0xFFFF);
                g_cnt[e + 4] = (int)((phi >> (e * 16)) & 0xFFFF);
            }
        }
    }
    __syncthreads();

    unsigned long long mylo = elo + base_lo[warp];
    unsigned long long myhi = ehi + base_hi[warp];
    const int base = t * 16;
#pragma unroll
    for (int k = 0; k < 16; k++) {
        const int r = toks[k];
        const int sh = (r & 3) * 16;
        const bool low = r < 4;
        const int p = (int)(((low ? mylo : myhi) >> sh) & 0xFFFF);
        const unsigned long long inc = 1ull << sh;
        if (low) mylo += inc; else myhi += inc;
        if (p < CAP) inv[r * CAP + p] = base + k;
    }
}

// ---------------------------------------------------------------------------
// Pass 3: gather (proven R10 form: plain __ldg + plain stores, 77.4us @78%
// DRAM; .cs hints measured slower). One CTA per output row.
// ---------------------------------------------------------------------------
__global__ void __launch_bounds__(256) gather_kernel(
    const float4* __restrict__ x,
    const int*   __restrict__ inv,
    float4* __restrict__ out)
{
    const int row = blockIdx.x;
    const int e = row >> 11;          // row / CAP
    const int p = row & (CAP - 1);
    float4* o = out + (size_t)row * D_VEC;
    const int t = threadIdx.x;

    if (p < g_cnt[e]) {
        const int src = __ldg(inv + row);      // uniform broadcast
        const float4* s = x + (size_t)src * D_VEC;
#pragma unroll
        for (int i = 0; i < 4; i++)
            o[t + 256 * i] = __ldg(s + t + 256 * i);
    } else {
        const float4 z = make_float4(0.f, 0.f, 0.f, 0.f);
#pragma unroll
        for (int i = 0; i < 4; i++)
            o[t + 256 * i] = z;
    }
}

// ---------------------------------------------------------------------------
extern "C" void kernel_launch(void* const* d_in, const int* in_sizes, int n_in,
                              void* d_out, int out_size)
{
    const float* x = (const float*)d_in[0];   // [8,2048,4096]
    const float* W = (const float*)d_in[1];   // [8,4096]
    const float* b = (const float*)d_in[2];   // [8]
    float* out = (float*)d_out;               // [16384,4096]

    int* routes;   cudaGetSymbolAddress((void**)&routes, g_routes);
    int* inv;      cudaGetSymbolAddress((void**)&inv,    g_inv);
    float* margin; cudaGetSymbolAddress((void**)&margin, g_margin);

    route_kernel<<<N_TOK / 16, 256>>>(
        (const float4*)x, (const float4*)W, b, routes, margin);
    refine_kernel<<<64, 256>>>(x, W, b, routes);
    scan_kernel<<<1, 1024>>>((const int4*)routes, inv);
    gather_kernel<<<N_TOK, 256>>>(
        (const float4*)x, inv, (float4*)out);
}